// round 5
// baseline (speedup 1.0000x reference)
#include <cuda_runtime.h>
#include <cuda_bf16.h>

#define NMAX 100352
#define EMAX 2000000
#define THREADS 256
#define FULL 0xffffffffu

// ---- scratch (device globals; allocation-free rule) ----
__device__ __align__(256) int   g_deg_s[NMAX];
__device__ __align__(256) int   g_deg_d[NMAX];
__device__ __align__(256) float g_ns[NMAX];
__device__ __align__(256) float g_nd[NMAX];
__device__ __align__(256) int   g_rowstart[NMAX + 1];
__device__ __align__(256) int   g_cursor[NMAX];
__device__ __align__(256) int   g_bsum[256];
__device__ __align__(256) int2  g_csr[EMAX];       // .x = src, .y = bits(ew)
__device__ __align__(256) float g_hx1[NMAX * 32];  // ns * (feat @ W1)
__device__ __align__(256) float g_h1x[NMAX * 32];  // relu(layer1 out)
__device__ __align__(256) float g_h2x[NMAX * 16];  // ns * (h1 @ W2)

// K0: zero degree counters
__global__ void k_zero(int n) {
    int i = blockIdx.x * blockDim.x + threadIdx.x;
    if (i < n) { g_deg_s[i] = 0; g_deg_d[i] = 0; }
}

// K1: integer degree histogram (4 edges/thread; int4 on src/dst proven OK)
__global__ void k_deg(const int* __restrict__ src, const int* __restrict__ dst, int e) {
    int t = blockIdx.x * blockDim.x + threadIdx.x;
    int base = t * 4;
    if (base + 3 < e) {
        int4 s4 = *(const int4*)(src + base);
        int4 d4 = *(const int4*)(dst + base);
        atomicAdd(&g_deg_s[s4.x], 1); atomicAdd(&g_deg_s[s4.y], 1);
        atomicAdd(&g_deg_s[s4.z], 1); atomicAdd(&g_deg_s[s4.w], 1);
        atomicAdd(&g_deg_d[d4.x], 1); atomicAdd(&g_deg_d[d4.y], 1);
        atomicAdd(&g_deg_d[d4.z], 1); atomicAdd(&g_deg_d[d4.w], 1);
    } else {
        for (int i = base; i < e; i++) {
            atomicAdd(&g_deg_s[src[i]], 1);
            atomicAdd(&g_deg_d[dst[i]], 1);
        }
    }
}

// K2: norms
__global__ void k_norm(int n) {
    int i = blockIdx.x * blockDim.x + threadIdx.x;
    if (i >= n) return;
    g_ns[i] = rsqrtf(fmaxf((float)g_deg_s[i], 1.0f));
    g_nd[i] = rsqrtf(fmaxf((float)g_deg_d[i], 1.0f));
}

// K3a: per-block (1024 elems) exclusive scan of in-degrees
__global__ void k_scanA(int n) {
    __shared__ int wsum[8];
    int b = blockIdx.x, t = threadIdx.x;
    int base = b * 1024 + t * 4;
    int v[4]; int s = 0;
#pragma unroll
    for (int j = 0; j < 4; j++) {
        v[j] = (base + j < n) ? g_deg_d[base + j] : 0;
        s += v[j];
    }
    int lane = t & 31, wid = t >> 5;
    int incl = s;
#pragma unroll
    for (int o = 1; o < 32; o <<= 1) {
        int x = __shfl_up_sync(FULL, incl, o);
        if (lane >= o) incl += x;
    }
    if (lane == 31) wsum[wid] = incl;
    __syncthreads();
    if (t < 8) {
        int ws = wsum[t];
#pragma unroll
        for (int o = 1; o < 8; o <<= 1) {
            int x = __shfl_up_sync(0xffu, ws, o);
            if ((int)t >= o) ws += x;
        }
        wsum[t] = ws;
    }
    __syncthreads();
    int excl = incl - s + (wid > 0 ? wsum[wid - 1] : 0);
    int run = excl;
#pragma unroll
    for (int j = 0; j < 4; j++) {
        if (base + j < n) g_rowstart[base + j] = run;
        run += v[j];
    }
    if (t == 255) g_bsum[b] = run;
}

// K3b: scan block sums (one warp, nb <= 128)
__global__ void k_scanB(int nb, int n, int e) {
    int lane = threadIdx.x;
    int v[4]; int s = 0;
#pragma unroll
    for (int j = 0; j < 4; j++) {
        int idx = lane * 4 + j;
        v[j] = (idx < nb) ? g_bsum[idx] : 0;
        s += v[j];
    }
    int incl = s;
#pragma unroll
    for (int o = 1; o < 32; o <<= 1) {
        int x = __shfl_up_sync(FULL, incl, o);
        if (lane >= o) incl += x;
    }
    int run = incl - s;
#pragma unroll
    for (int j = 0; j < 4; j++) {
        int idx = lane * 4 + j;
        if (idx < nb) g_bsum[idx] = run;
        run += v[j];
    }
    if (lane == 0) g_rowstart[n] = e;
}

// K3c: add block offsets; init cursors
__global__ void k_scanC(int n) {
    int i = blockIdx.x * blockDim.x + threadIdx.x;
    if (i >= n) return;
    int rs = g_rowstart[i] + g_bsum[i >> 10];
    g_rowstart[i] = rs;
    g_cursor[i] = rs;
}

// K4: CSR fill; weight = raw ew (ns folded into pre-transform)
__global__ void k_fill(const int* __restrict__ src, const int* __restrict__ dst,
                       const float* __restrict__ ew, int e) {
    int i = blockIdx.x * blockDim.x + threadIdx.x;
    if (i >= e) return;
    int s = src[i], d = dst[i];
    float w = __ldg(ew + i);
    int pos = atomicAdd(&g_cursor[d], 1);
    g_csr[pos] = make_int2(s, __float_as_int(w));
}

// K5: pre-transform 1: g_hx1[n,:] = ns[n] * (feat[n,:] @ W1)
// smem-staged (rows padded to 33), warp per 32 nodes, lane = out column.
__global__ void __launch_bounds__(THREADS) k_xform1(const float* __restrict__ feat,
                                                    const float* __restrict__ W1, int n) {
    __shared__ float sf[256 * 33];
    int tid = threadIdx.x;
    int lane = tid & 31, w = tid >> 5;
    float w1[32];
#pragma unroll
    for (int k = 0; k < 32; k++) w1[k] = __ldg(W1 + k * 32 + lane);

    int base = blockIdx.x * 256;
    int cnt = min(256, n - base);            // nodes in this block
    for (int i = tid; i < cnt * 32; i += 256) {
        int node = i >> 5, col = i & 31;
        sf[node * 33 + col] = feat[(size_t)(base + node) * 32 + col];
    }
    __syncthreads();

    for (int t = 0; t < 32; t += 2) {
        int l0 = w * 32 + t, l1 = l0 + 1;
        if (l0 >= cnt) break;
        float acc0 = 0.f, acc1 = 0.f;
        const float* r0 = sf + l0 * 33;
        const float* r1 = sf + l1 * 33;
        bool has1 = (l1 < cnt);
#pragma unroll
        for (int k = 0; k < 32; k++) {
            acc0 = fmaf(r0[k], w1[k], acc0);
            acc1 = fmaf(r1[k], w1[k], acc1);
        }
        int n0 = base + l0;
        g_hx1[(size_t)n0 * 32 + lane] = acc0 * g_ns[n0];
        if (has1) g_hx1[(size_t)(n0 + 1) * 32 + lane] = acc1 * g_ns[n0 + 1];
    }
}

// K6: gather layer 1: h1x = relu(nd * seg_sum(ew * g_hx1[src]) + b1)
// warp per node; 4 subgroups x 8 lanes; float4 per lane; 16 edges/iter.
__global__ void __launch_bounds__(THREADS) k_gather1(const float* __restrict__ b1, int n) {
    int lane = threadIdx.x & 31;
    int sub = lane >> 3;
    int comp = lane & 7;
    float4 bl = make_float4(__ldg(b1 + comp * 4), __ldg(b1 + comp * 4 + 1),
                            __ldg(b1 + comp * 4 + 2), __ldg(b1 + comp * 4 + 3));

    int warpId = (blockIdx.x * blockDim.x + threadIdx.x) >> 5;
    int nwarps = (gridDim.x * blockDim.x) >> 5;

    for (int node = warpId; node < n; node += nwarps) {
        int rs = g_rowstart[node], re = g_rowstart[node + 1];
        float4 acc = make_float4(0.f, 0.f, 0.f, 0.f);
        for (int base = rs; base < re; base += 16) {
#pragma unroll
            for (int u = 0; u < 4; u++) {
                int i = base + u * 4 + sub;
                if (i < re) {
                    int2 eg = g_csr[i];
                    float wt = __int_as_float(eg.y);
                    float4 v = ((const float4*)(g_hx1 + (size_t)eg.x * 32))[comp];
                    acc.x = fmaf(wt, v.x, acc.x); acc.y = fmaf(wt, v.y, acc.y);
                    acc.z = fmaf(wt, v.z, acc.z); acc.w = fmaf(wt, v.w, acc.w);
                }
            }
        }
        acc.x += __shfl_xor_sync(FULL, acc.x, 8);
        acc.y += __shfl_xor_sync(FULL, acc.y, 8);
        acc.z += __shfl_xor_sync(FULL, acc.z, 8);
        acc.w += __shfl_xor_sync(FULL, acc.w, 8);
        acc.x += __shfl_xor_sync(FULL, acc.x, 16);
        acc.y += __shfl_xor_sync(FULL, acc.y, 16);
        acc.z += __shfl_xor_sync(FULL, acc.z, 16);
        acc.w += __shfl_xor_sync(FULL, acc.w, 16);
        if (sub == 0) {
            float nd = g_nd[node];
            float4 y;
            y.x = fmaxf(fmaf(acc.x, nd, bl.x), 0.f);
            y.y = fmaxf(fmaf(acc.y, nd, bl.y), 0.f);
            y.z = fmaxf(fmaf(acc.z, nd, bl.z), 0.f);
            y.w = fmaxf(fmaf(acc.w, nd, bl.w), 0.f);
            ((float4*)(g_h1x + (size_t)node * 32))[comp] = y;
        }
    }
}

// K7: pre-transform 2: g_h2x[n,:] = (ns[n] * h1x[n,:]) @ W2
// smem-staged with ns folded in; half-warp per node, j = out column.
__global__ void __launch_bounds__(THREADS) k_xform2(const float* __restrict__ W2, int n) {
    __shared__ float sf[256 * 33];
    int tid = threadIdx.x;
    int lane = tid & 31, w = tid >> 5;
    int p = lane >> 4, j = lane & 15;
    float w2[32];
#pragma unroll
    for (int k = 0; k < 32; k++) w2[k] = __ldg(W2 + k * 16 + j);

    int base = blockIdx.x * 256;
    int cnt = min(256, n - base);
    for (int i = tid; i < cnt * 32; i += 256) {
        int node = i >> 5, col = i & 31;
        sf[node * 33 + col] = g_h1x[(size_t)(base + node) * 32 + col] * g_ns[base + node];
    }
    __syncthreads();

    for (int t = 0; t < 32; t += 2) {
        int l = w * 32 + t + p;
        if (l >= cnt) continue;
        float acc = 0.f;
        const float* r = sf + l * 33;
#pragma unroll
        for (int k = 0; k < 32; k++) acc = fmaf(r[k], w2[k], acc);
        g_h2x[(size_t)(base + l) * 16 + j] = acc;
    }
}

// K8: gather layer 2: out = nd * seg_sum(ew * g_h2x[src]) + b2
// warp per node; 8 subgroups x 4 lanes; float4 per lane; 32 edges/iter.
__global__ void __launch_bounds__(THREADS) k_gather2(const float* __restrict__ b2,
                                                     float* __restrict__ out, int n) {
    int lane = threadIdx.x & 31;
    int sub = lane >> 2;
    int comp = lane & 3;
    float4 bl = make_float4(__ldg(b2 + comp * 4), __ldg(b2 + comp * 4 + 1),
                            __ldg(b2 + comp * 4 + 2), __ldg(b2 + comp * 4 + 3));

    int warpId = (blockIdx.x * blockDim.x + threadIdx.x) >> 5;
    int nwarps = (gridDim.x * blockDim.x) >> 5;

    for (int node = warpId; node < n; node += nwarps) {
        int rs = g_rowstart[node], re = g_rowstart[node + 1];
        float4 acc = make_float4(0.f, 0.f, 0.f, 0.f);
        for (int base = rs; base < re; base += 32) {
#pragma unroll
            for (int u = 0; u < 4; u++) {
                int i = base + u * 8 + sub;
                if (i < re) {
                    int2 eg = g_csr[i];
                    float wt = __int_as_float(eg.y);
                    float4 v = ((const float4*)(g_h2x + (size_t)eg.x * 16))[comp];
                    acc.x = fmaf(wt, v.x, acc.x); acc.y = fmaf(wt, v.y, acc.y);
                    acc.z = fmaf(wt, v.z, acc.z); acc.w = fmaf(wt, v.w, acc.w);
                }
            }
        }
#pragma unroll
        for (int o = 4; o < 32; o <<= 1) {
            acc.x += __shfl_xor_sync(FULL, acc.x, o);
            acc.y += __shfl_xor_sync(FULL, acc.y, o);
            acc.z += __shfl_xor_sync(FULL, acc.z, o);
            acc.w += __shfl_xor_sync(FULL, acc.w, o);
        }
        if (sub == 0) {
            float nd = g_nd[node];
            float4 y;
            y.x = fmaf(acc.x, nd, bl.x);
            y.y = fmaf(acc.y, nd, bl.y);
            y.z = fmaf(acc.z, nd, bl.z);
            y.w = fmaf(acc.w, nd, bl.w);
            ((float4*)(out + (size_t)node * 16))[comp] = y;  // out proven 16B-aligned (R1)
        }
    }
}

static inline int cdiv(long long a, int b) { return (int)((a + b - 1) / b); }

extern "C" void kernel_launch(void* const* d_in, const int* in_sizes, int n_in,
                              void* d_out, int out_size) {
    const float* feat = (const float*)d_in[0];
    const int*   src  = (const int*)d_in[1];
    const int*   dst  = (const int*)d_in[2];
    const float* ew   = (const float*)d_in[3];
    const float* W1   = (const float*)d_in[4];
    const float* b1   = (const float*)d_in[5];
    const float* W2   = (const float*)d_in[6];
    const float* b2   = (const float*)d_in[7];
    float* out = (float*)d_out;

    int n = in_sizes[0] / 32;
    int e = in_sizes[1];
    int nb = cdiv(n, 1024);

    const int GBLOCKS = 592;  // 4 blocks/SM

    k_zero   <<<cdiv(n, THREADS), THREADS>>>(n);
    k_deg    <<<cdiv(cdiv(e, 4), THREADS), THREADS>>>(src, dst, e);
    k_norm   <<<cdiv(n, THREADS), THREADS>>>(n);
    k_scanA  <<<nb, THREADS>>>(n);
    k_scanB  <<<1, 32>>>(nb, n, e);
    k_scanC  <<<cdiv(n, THREADS), THREADS>>>(n);
    k_fill   <<<cdiv(e, THREADS), THREADS>>>(src, dst, ew, e);
    k_xform1 <<<cdiv(n, 256), THREADS>>>(feat, W1, n);
    k_gather1<<<GBLOCKS, THREADS>>>(b1, n);
    k_xform2 <<<cdiv(n, 256), THREADS>>>(W2, n);
    k_gather2<<<GBLOCKS, THREADS>>>(b2, out, n);
}

// round 7
// speedup vs baseline: 1.0422x; 1.0422x over previous
#include <cuda_runtime.h>
#include <cuda_bf16.h>

#define NMAX 100352
#define EMAX 2000000
#define THREADS 256
#define FULL 0xffffffffu

// ---- scratch (device globals; zero-initialized at module load) ----
// g_deg_* are re-zeroed at the END of each launch (k_scanC) so every
// launch sees them zeroed -> deterministic, identical work per call.
__device__ __align__(256) int   g_deg_s[NMAX];
__device__ __align__(256) int   g_deg_d[NMAX];
__device__ __align__(256) float g_ns[NMAX];
__device__ __align__(256) float g_nd[NMAX];
__device__ __align__(256) int   g_rowstart[NMAX + 1];
__device__ __align__(256) int   g_cursor[NMAX];
__device__ __align__(256) int   g_bsum[256];
__device__ __align__(256) int2  g_csr[EMAX];       // .x = src, .y = bits(ew)
__device__ __align__(256) float g_hx1[NMAX * 32];  // ns * (feat @ W1)
__device__ __align__(256) float g_h2x[NMAX * 16];  // ns * (h1 @ W2)

// K1: integer degree histogram (4 edges/thread)
__global__ void k_deg(const int* __restrict__ src, const int* __restrict__ dst, int e) {
    int t = blockIdx.x * blockDim.x + threadIdx.x;
    int base = t * 4;
    if (base + 3 < e) {
        int4 s4 = *(const int4*)(src + base);
        int4 d4 = *(const int4*)(dst + base);
        atomicAdd(&g_deg_s[s4.x], 1); atomicAdd(&g_deg_s[s4.y], 1);
        atomicAdd(&g_deg_s[s4.z], 1); atomicAdd(&g_deg_s[s4.w], 1);
        atomicAdd(&g_deg_d[d4.x], 1); atomicAdd(&g_deg_d[d4.y], 1);
        atomicAdd(&g_deg_d[d4.z], 1); atomicAdd(&g_deg_d[d4.w], 1);
    } else {
        for (int i = base; i < e; i++) {
            atomicAdd(&g_deg_s[src[i]], 1);
            atomicAdd(&g_deg_d[dst[i]], 1);
        }
    }
}

// K2: per-block (1024 elems) exclusive scan of in-degrees + norms
__global__ void k_scanA(int n) {
    __shared__ int wsum[8];
    int b = blockIdx.x, t = threadIdx.x;
    int base = b * 1024 + t * 4;
    int v[4]; int s = 0;
#pragma unroll
    for (int j = 0; j < 4; j++) {
        v[j] = (base + j < n) ? g_deg_d[base + j] : 0;
        s += v[j];
    }
#pragma unroll
    for (int j = 0; j < 4; j++) {
        int i = base + j;
        if (i < n) {
            g_nd[i] = rsqrtf(fmaxf((float)v[j], 1.0f));
            g_ns[i] = rsqrtf(fmaxf((float)g_deg_s[i], 1.0f));
        }
    }
    int lane = t & 31, wid = t >> 5;
    int incl = s;
#pragma unroll
    for (int o = 1; o < 32; o <<= 1) {
        int x = __shfl_up_sync(FULL, incl, o);
        if (lane >= o) incl += x;
    }
    if (lane == 31) wsum[wid] = incl;
    __syncthreads();
    if (t < 8) {
        int ws = wsum[t];
#pragma unroll
        for (int o = 1; o < 8; o <<= 1) {
            int x = __shfl_up_sync(0xffu, ws, o);
            if ((int)t >= o) ws += x;
        }
        wsum[t] = ws;
    }
    __syncthreads();
    int excl = incl - s + (wid > 0 ? wsum[wid - 1] : 0);
    int run = excl;
#pragma unroll
    for (int j = 0; j < 4; j++) {
        if (base + j < n) g_rowstart[base + j] = run;
        run += v[j];
    }
    if (t == 255) g_bsum[b] = run;
}

// K3: scan block sums (one warp, nb <= 128)
__global__ void k_scanB(int nb, int n, int e) {
    int lane = threadIdx.x;
    int v[4]; int s = 0;
#pragma unroll
    for (int j = 0; j < 4; j++) {
        int idx = lane * 4 + j;
        v[j] = (idx < nb) ? g_bsum[idx] : 0;
        s += v[j];
    }
    int incl = s;
#pragma unroll
    for (int o = 1; o < 32; o <<= 1) {
        int x = __shfl_up_sync(FULL, incl, o);
        if (lane >= o) incl += x;
    }
    int run = incl - s;
#pragma unroll
    for (int j = 0; j < 4; j++) {
        int idx = lane * 4 + j;
        if (idx < nb) g_bsum[idx] = run;
        run += v[j];
    }
    if (lane == 0) g_rowstart[n] = e;
}

// K4: add block offsets; init cursors; re-zero degree tables for next launch
__global__ void k_scanC(int n) {
    int i = blockIdx.x * blockDim.x + threadIdx.x;
    if (i >= n) return;
    int rs = g_rowstart[i] + g_bsum[i >> 10];
    g_rowstart[i] = rs;
    g_cursor[i] = rs;
    g_deg_s[i] = 0;
    g_deg_d[i] = 0;
}

// K5: heterogeneous: blocks [0,FB) fill CSR; blocks [FB,FB+XB) do xform1.
__global__ void __launch_bounds__(THREADS) k_fillx(
        const int* __restrict__ src, const int* __restrict__ dst,
        const float* __restrict__ ew, const float* __restrict__ feat,
        const float* __restrict__ W1, int n, int e, int FB) {
    if ((int)blockIdx.x < FB) {
        int i = blockIdx.x * THREADS + threadIdx.x;
        if (i < e) {
            int s = src[i], d = dst[i];
            float w = __ldg(ew + i);
            int pos = atomicAdd(&g_cursor[d], 1);
            g_csr[pos] = make_int2(s, __float_as_int(w));
        }
        return;
    }
    __shared__ float sf[256 * 33];
    int tid = threadIdx.x;
    int lane = tid & 31, w = tid >> 5;
    float w1[32];
#pragma unroll
    for (int k = 0; k < 32; k++) w1[k] = __ldg(W1 + k * 32 + lane);

    int base = (blockIdx.x - FB) * 256;
    int cnt = min(256, n - base);
    for (int i = tid; i < cnt * 32; i += 256) {
        int node = i >> 5, col = i & 31;
        sf[node * 33 + col] = feat[(size_t)(base + node) * 32 + col];
    }
    __syncthreads();

    for (int t = 0; t < 32; t += 2) {
        int l0 = w * 32 + t, l1 = l0 + 1;
        if (l0 >= cnt) break;
        float acc0 = 0.f, acc1 = 0.f;
        const float* r0 = sf + l0 * 33;
        const float* r1 = sf + l1 * 33;
        bool has1 = (l1 < cnt);
#pragma unroll
        for (int k = 0; k < 32; k++) {
            acc0 = fmaf(r0[k], w1[k], acc0);
            acc1 = fmaf(r1[k], w1[k], acc1);
        }
        int n0 = base + l0;
        g_hx1[(size_t)n0 * 32 + lane] = acc0 * g_ns[n0];
        if (has1) g_hx1[(size_t)(n0 + 1) * 32 + lane] = acc1 * g_ns[n0 + 1];
    }
}

// K6: gather layer 1 + fused xform2:
//   agg = seg_sum(ew * g_hx1[src]);  h = relu(nd*agg + b1) * ns;
//   g_h2x[node,:] = h @ W2
__global__ void __launch_bounds__(THREADS) k_gather1(
        const float* __restrict__ b1, const float* __restrict__ W2, int n) {
    __shared__ float sW2[512];   // 32 x 16
    __shared__ float sb1[32];
    int tid = threadIdx.x;
    // FIX (R6 bug): strided loads — block has only 256 threads, W2 has 512 elems.
    for (int i = tid; i < 512; i += THREADS) sW2[i] = __ldg(W2 + i);
    for (int i = tid; i < 32;  i += THREADS) sb1[i] = __ldg(b1 + i);
    __syncthreads();

    int lane = tid & 31;
    int sub = lane >> 3;
    int comp = lane & 7;
    int j = lane & 15;

    int warpId = (blockIdx.x * blockDim.x + tid) >> 5;
    int nwarps = (gridDim.x * blockDim.x) >> 5;

    for (int node = warpId; node < n; node += nwarps) {
        int rs = g_rowstart[node], re = g_rowstart[node + 1];
        float4 acc = make_float4(0.f, 0.f, 0.f, 0.f);
        for (int base = rs; base < re; base += 16) {
#pragma unroll
            for (int u = 0; u < 4; u++) {
                int i = base + u * 4 + sub;
                if (i < re) {
                    int2 eg = g_csr[i];
                    float wt = __int_as_float(eg.y);
                    float4 v = ((const float4*)(g_hx1 + (size_t)eg.x * 32))[comp];
                    acc.x = fmaf(wt, v.x, acc.x); acc.y = fmaf(wt, v.y, acc.y);
                    acc.z = fmaf(wt, v.z, acc.z); acc.w = fmaf(wt, v.w, acc.w);
                }
            }
        }
        // xor-reduce: every lane ends with the full aggregate for its comp.
        acc.x += __shfl_xor_sync(FULL, acc.x, 8);
        acc.y += __shfl_xor_sync(FULL, acc.y, 8);
        acc.z += __shfl_xor_sync(FULL, acc.z, 8);
        acc.w += __shfl_xor_sync(FULL, acc.w, 8);
        acc.x += __shfl_xor_sync(FULL, acc.x, 16);
        acc.y += __shfl_xor_sync(FULL, acc.y, 16);
        acc.z += __shfl_xor_sync(FULL, acc.z, 16);
        acc.w += __shfl_xor_sync(FULL, acc.w, 16);

        float nd = g_nd[node];
        float ns = g_ns[node];
        float4 h;
        h.x = fmaxf(fmaf(acc.x, nd, sb1[comp * 4 + 0]), 0.f) * ns;
        h.y = fmaxf(fmaf(acc.y, nd, sb1[comp * 4 + 1]), 0.f) * ns;
        h.z = fmaxf(fmaf(acc.z, nd, sb1[comp * 4 + 2]), 0.f) * ns;
        h.w = fmaxf(fmaf(acc.w, nd, sb1[comp * 4 + 3]), 0.f) * ns;

        // fused 32->16 GEMM: y_j = sum_k h_k * W2[k][j]
        float y = 0.f;
#pragma unroll
        for (int m = 0; m < 8; m++) {
            float hx = __shfl_sync(FULL, h.x, m);
            float hy = __shfl_sync(FULL, h.y, m);
            float hz = __shfl_sync(FULL, h.z, m);
            float hw = __shfl_sync(FULL, h.w, m);
            y = fmaf(hx, sW2[(4 * m + 0) * 16 + j], y);
            y = fmaf(hy, sW2[(4 * m + 1) * 16 + j], y);
            y = fmaf(hz, sW2[(4 * m + 2) * 16 + j], y);
            y = fmaf(hw, sW2[(4 * m + 3) * 16 + j], y);
        }
        if (lane < 16) g_h2x[(size_t)node * 16 + lane] = y;
    }
}

// K7: gather layer 2: out = nd * seg_sum(ew * g_h2x[src]) + b2
__global__ void __launch_bounds__(THREADS) k_gather2(const float* __restrict__ b2,
                                                     float* __restrict__ out, int n) {
    int lane = threadIdx.x & 31;
    int sub = lane >> 2;
    int comp = lane & 3;
    float4 bl = make_float4(__ldg(b2 + comp * 4), __ldg(b2 + comp * 4 + 1),
                            __ldg(b2 + comp * 4 + 2), __ldg(b2 + comp * 4 + 3));

    int warpId = (blockIdx.x * blockDim.x + threadIdx.x) >> 5;
    int nwarps = (gridDim.x * blockDim.x) >> 5;

    for (int node = warpId; node < n; node += nwarps) {
        int rs = g_rowstart[node], re = g_rowstart[node + 1];
        float4 acc = make_float4(0.f, 0.f, 0.f, 0.f);
        for (int base = rs; base < re; base += 32) {
#pragma unroll
            for (int u = 0; u < 4; u++) {
                int i = base + u * 8 + sub;
                if (i < re) {
                    int2 eg = g_csr[i];
                    float wt = __int_as_float(eg.y);
                    float4 v = ((const float4*)(g_h2x + (size_t)eg.x * 16))[comp];
                    acc.x = fmaf(wt, v.x, acc.x); acc.y = fmaf(wt, v.y, acc.y);
                    acc.z = fmaf(wt, v.z, acc.z); acc.w = fmaf(wt, v.w, acc.w);
                }
            }
        }
#pragma unroll
        for (int o = 4; o < 32; o <<= 1) {
            acc.x += __shfl_xor_sync(FULL, acc.x, o);
            acc.y += __shfl_xor_sync(FULL, acc.y, o);
            acc.z += __shfl_xor_sync(FULL, acc.z, o);
            acc.w += __shfl_xor_sync(FULL, acc.w, o);
        }
        if (sub == 0) {
            float nd = g_nd[node];
            float4 y;
            y.x = fmaf(acc.x, nd, bl.x);
            y.y = fmaf(acc.y, nd, bl.y);
            y.z = fmaf(acc.z, nd, bl.z);
            y.w = fmaf(acc.w, nd, bl.w);
            ((float4*)(out + (size_t)node * 16))[comp] = y;
        }
    }
}

static inline int cdiv(long long a, int b) { return (int)((a + b - 1) / b); }

extern "C" void kernel_launch(void* const* d_in, const int* in_sizes, int n_in,
                              void* d_out, int out_size) {
    const float* feat = (const float*)d_in[0];
    const int*   src  = (const int*)d_in[1];
    const int*   dst  = (const int*)d_in[2];
    const float* ew   = (const float*)d_in[3];
    const float* W1   = (const float*)d_in[4];
    const float* b1   = (const float*)d_in[5];
    const float* W2   = (const float*)d_in[6];
    const float* b2   = (const float*)d_in[7];
    float* out = (float*)d_out;

    int n = in_sizes[0] / 32;
    int e = in_sizes[1];
    int nb = cdiv(n, 1024);
    int FB = cdiv(e, THREADS);       // fill blocks
    int XB = cdiv(n, 256);           // xform1 blocks

    const int GBLOCKS = 592;  // 4 blocks/SM

    k_deg    <<<cdiv(cdiv(e, 4), THREADS), THREADS>>>(src, dst, e);
    k_scanA  <<<nb, THREADS>>>(n);
    k_scanB  <<<1, 32>>>(nb, n, e);
    k_scanC  <<<cdiv(n, THREADS), THREADS>>>(n);
    k_fillx  <<<FB + XB, THREADS>>>(src, dst, ew, feat, W1, n, e, FB);
    k_gather1<<<GBLOCKS, THREADS>>>(b1, W2, n);
    k_gather2<<<GBLOCKS, THREADS>>>(b2, out, n);
}